// round 16
// baseline (speedup 1.0000x reference)
#include <cuda_runtime.h>
#include <cuda_fp16.h>
#include <cstdint>

#define NN   100000
#define EE   640000
#define HD   128
#define NT   3
#define PD   64
#define NPOS 513
#define VEMB 96
#define NT64  1563         // ceil(100000/64)
#define APW  68            // A/H tile pitch in 4B words (136 halves)

// ---------------- device scratch ----------------
static __device__ unsigned d_hhA[NN * 64];    // fp16 h state (half2-packed), ping
static __device__ unsigned d_hhB[NN * 64];    // fp16 h state, pong
static __device__ unsigned d_h0h[NN * 64];    // fp16 h0 (half2-packed)
static __device__ unsigned d_gh[NPOS * 64];   // fp16 gate table (half2-packed)
static __device__ float d_cntT[NT * NN];
static __device__ float d_invden[NN];
static __device__ int   d_degi[NN];
static __device__ int   d_fill[NN];
static __device__ int   d_rowtmp[NN];
static __device__ int   d_rowp[NN];
static __device__ int   d_bsum[98];
static __device__ unsigned d_epk[EE];
static __device__ __align__(16) unsigned d_Bh[11 * 8192];  // fp16 weight chunks (32KB each)

// ---------------- helpers ----------------
__device__ __forceinline__ float fsig(float x) {
    return __fdividef(1.0f, 1.0f + __expf(-x));
}
__device__ __forceinline__ float ftanh(float x) {
    return 1.0f - __fdividef(2.0f, __expf(2.0f * x) + 1.0f);
}
__device__ __forceinline__ unsigned packh2(float lo, float hi) {
    __half2 h = __floats2half2_rn(lo, hi);
    return *(unsigned*)&h;
}
__device__ __forceinline__ float2 unph2(unsigned u) {
    return __half22float2(*(__half2*)&u);
}

#define MMA16(acc0, acc1, acc2, acc3, a0, a1, a2, a3, bx, by)                    \
    asm volatile("mma.sync.aligned.m16n8k16.row.col.f32.f16.f16.f32 "            \
                 "{%0,%1,%2,%3}, {%4,%5,%6,%7}, {%8,%9}, {%0,%1,%2,%3};"         \
                 : "+f"(acc0), "+f"(acc1), "+f"(acc2), "+f"(acc3)                \
                 : "r"(a0), "r"(a1), "r"(a2), "r"(a3), "r"(bx), "r"(by))

// 16x64 warp tile (readout): acc[8][4]
__device__ __forceinline__ void gemm_h(const unsigned* __restrict__ Aw,
                                       const unsigned* __restrict__ Bs,
                                       int r0, int c0, int g, int tig,
                                       float acc[8][4]) {
#pragma unroll
    for (int ks = 0; ks < 8; ks++) {
        const unsigned* ap = Aw + (r0 + g) * APW + ks * 8 + tig;
        unsigned a0 = ap[0], a1 = ap[8 * APW], a2 = ap[4], a3 = ap[8 * APW + 4];
        const uint2* bp = (const uint2*)Bs + ks * 512 + (c0 + g) * 4 + tig;
#pragma unroll
        for (int nt = 0; nt < 8; nt++) {
            uint2 b = bp[nt * 32];
            MMA16(acc[nt][0], acc[nt][1], acc[nt][2], acc[nt][3],
                  a0, a1, a2, a3, b.x, b.y);
        }
    }
}

// 32x32 warp tile over HALF a K-chunk, group-local B (32 cols, 4KB): acc[4][8]
__device__ __forceinline__ void gemm_half(const unsigned* __restrict__ Aw,
                                          const unsigned* __restrict__ Bg,
                                          int ksb, int r0, int g, int tig,
                                          float acc[4][8]) {
#pragma unroll
    for (int ks = 0; ks < 4; ks++) {
        const unsigned* ap = Aw + (r0 + g) * APW + (ksb + ks) * 8 + tig;
        unsigned a0 = ap[0],            a1 = ap[8 * APW],
                 a2 = ap[4],            a3 = ap[8 * APW + 4];
        unsigned a4 = ap[16 * APW],     a5 = ap[24 * APW],
                 a6 = ap[16 * APW + 4], a7 = ap[24 * APW + 4];
        const uint2* bp = (const uint2*)Bg + ks * 128 + g * 4 + tig;
#pragma unroll
        for (int nt = 0; nt < 4; nt++) {
            uint2 b = bp[nt * 32];
            MMA16(acc[nt][0], acc[nt][1], acc[nt][2], acc[nt][3],
                  a0, a1, a2, a3, b.x, b.y);
            MMA16(acc[nt][4], acc[nt][5], acc[nt][6], acc[nt][7],
                  a4, a5, a6, a7, b.x, b.y);
        }
    }
}

#define ZACC4(acc) do { _Pragma("unroll") for (int _n = 0; _n < 8; _n++) \
    { acc[_n][0]=0.f; acc[_n][1]=0.f; acc[_n][2]=0.f; acc[_n][3]=0.f; } } while (0)
#define ZACCT(acc) do { _Pragma("unroll") for (int _n = 0; _n < 4; _n++) \
    _Pragma("unroll") for (int _i = 0; _i < 8; _i++) acc[_n][_i]=0.f; } while (0)

// group-local cp.async prefetch: 64 threads fetch this group's 32 cols of one
// half-chunk (4 x 1KB, one per k-step)
#define PREF_G(sbase, ch, hf) do {                                                \
    const char* _g = (const char*)d_Bh + (ch) * 32768 + (hf) * 16384              \
                     + c0 * 32 + gtid * 16;                                       \
    _Pragma("unroll") for (int _k = 0; _k < 4; _k++) {                            \
        asm volatile("cp.async.cg.shared.global [%0], [%1], 16;"                  \
                     :: "r"((sbase) + _k * 1024 + gtid * 16), "l"(_g + _k * 4096)); \
    }                                                                             \
    asm volatile("cp.async.commit_group;" ::: "memory");                          \
} while (0)
#define CP_WAIT(n) asm volatile("cp.async.wait_group %0;" :: "n"(n) : "memory")
#define BARG() asm volatile("bar.sync %0, 64;" :: "r"(cg + 1) : "memory")

// group pipeline step: wait half, pair-barrier, mma, pair-barrier, prefetch ahead
#define GSTEP(bufv, Aw, ksb, bufa, pch, phf) do {                                 \
    CP_WAIT(1); BARG();                                                           \
    gemm_half(Aw, bufv, ksb, r0, g, tig, acc);                                    \
    BARG();                                                                       \
    PREF_G(bufa, pch, phf); } while (0)
#define GSTEP_NP(bufv, Aw, ksb, wn) do {                                          \
    CP_WAIT(wn); BARG();                                                          \
    gemm_half(Aw, bufv, ksb, r0, g, tig, acc); } while (0)

// 256-thread staging for readout kernel
#define STAGE_B256(Bs, ch) do { __syncthreads();                                  \
    for (int _it = 0; _it < 8; _it++) {                                           \
        int _i = _it * 256 + tid;                                                 \
        *(uint4*)&(Bs)[_i * 4] = *(const uint4*)&d_Bh[(ch) * 8192 + _i * 4];      \
    } __syncthreads(); } while (0)

// ---------------- prep kernels ----------------
__global__ void gate_kernel(const float* __restrict__ pos_enc, const float* __restrict__ Wg,
                            const float* __restrict__ bg) {
    int p = blockIdx.x, j = threadIdx.x;   // j in [0,64)
    __shared__ float pe[PD];
    pe[j] = pos_enc[p * PD + j];
    __syncthreads();
    float a0 = bg[2 * j], a1 = bg[2 * j + 1];
#pragma unroll
    for (int k = 0; k < PD; k++) {
        float w = pe[k];
        a0 = fmaf(w, Wg[k * HD + 2 * j], a0);
        a1 = fmaf(w, Wg[k * HD + 2 * j + 1], a1);
    }
    d_gh[p * 64 + j] = packh2(2.0f / (1.0f + expf(-a0)), 2.0f / (1.0f + expf(-a1)));
}

__global__ void init_h(const int* __restrict__ xidx, const float* __restrict__ sel,
                       const float* __restrict__ emb) {
    int v = blockIdx.x, j = threadIdx.x;
    float val = (j < VEMB) ? emb[xidx[v] * VEMB + j] : sel[v * 32 + (j - VEMB)];
    float nb = __shfl_down_sync(0xffffffffu, val, 1);
    if (!(j & 1)) {
        unsigned pk = packh2(val, nb);
        d_hhA[v * 64 + (j >> 1)] = pk;
        d_h0h[v * 64 + (j >> 1)] = pk;
    }
}

__global__ void zero_misc() {
    int i = blockIdx.x * blockDim.x + threadIdx.x;
    if (i < NT * NN) d_cntT[i] = 0.0f;
    if (i < NN) { d_degi[i] = 0; d_fill[i] = 0; }
}
__global__ void cnt_kernel(const int* __restrict__ dst, const int* __restrict__ etype) {
    int e = blockIdx.x * blockDim.x + threadIdx.x;
    if (e < EE) {
        atomicAdd(&d_cntT[etype[e] * NN + dst[e]], 1.0f);
        atomicAdd(&d_degi[dst[e]], 1);
    }
}
__global__ void invden_kernel() {
    int v = blockIdx.x * blockDim.x + threadIdx.x;
    if (v < NN) d_invden[v] = 1.0f / fmaxf((float)d_degi[v], 1.0f);
}

__global__ void scanA() {
    __shared__ int s[1024];
    int b = blockIdx.x, t = threadIdx.x;
    int i = b * 1024 + t;
    s[t] = (i < NN) ? d_degi[i] : 0;
    __syncthreads();
#pragma unroll
    for (int off = 1; off < 1024; off <<= 1) {
        int x = (t >= off) ? s[t - off] : 0;
        __syncthreads();
        s[t] += x;
        __syncthreads();
    }
    if (i < NN) d_rowtmp[i] = s[t];
    if (t == 1023) d_bsum[b] = s[1023];
}
__global__ void scanB() {
    if (threadIdx.x == 0) {
        int run = 0;
        for (int b = 0; b < 98; b++) { int x = d_bsum[b]; d_bsum[b] = run; run += x; }
    }
}
__global__ void scanC() {
    int i = blockIdx.x * blockDim.x + threadIdx.x;
    if (i < NN) d_rowp[i] = d_rowtmp[i] - d_degi[i] + d_bsum[i >> 10];
}
__global__ void fill_kernel(const int* __restrict__ src, const int* __restrict__ dst,
                            const int* __restrict__ etype, const int* __restrict__ epos) {
    int e = blockIdx.x * blockDim.x + threadIdx.x;
    if (e < EE) {
        int dv = dst[e];
        int slot = d_rowp[dv] + atomicAdd(&d_fill[dv], 1);
        d_epk[slot] = (unsigned)src[e] | ((unsigned)epos[e] << 17) | ((unsigned)etype[e] << 27);
    }
}

// chunks: 0..2 Wt[t] (B[k][n]=Wt[t][k][n]); 3..5 Wih r/z/n (B[k][o]=Wih[o][k]);
//         6..8 Whh r/z/n; 9..10 W1 halves
__global__ void bprep(const float* __restrict__ Wt, const float* __restrict__ Wih,
                      const float* __restrict__ Whh, const float* __restrict__ W1) {
    int c = blockIdx.x;
    for (int i = threadIdx.x; i < 8192; i += blockDim.x) {
        int j = i & 1, tig = (i >> 1) & 3, n = (i >> 3) & 127, ks = i >> 10;
        int k0 = ks * 16 + j * 8 + tig * 2;
        float lo, hi;
        if (c < 3)       { lo = Wt[c * 16384 + k0 * HD + n];        hi = Wt[c * 16384 + (k0 + 1) * HD + n]; }
        else if (c < 6)  { lo = Wih[((c - 3) * 128 + n) * HD + k0]; hi = Wih[((c - 3) * 128 + n) * HD + k0 + 1]; }
        else if (c < 9)  { lo = Whh[((c - 6) * 128 + n) * HD + k0]; hi = Whh[((c - 6) * 128 + n) * HD + k0 + 1]; }
        else if (c == 9) { lo = W1[k0 * HD + n];                    hi = W1[(k0 + 1) * HD + n]; }
        else             { lo = W1[(128 + k0) * HD + n];            hi = W1[(129 + k0) * HD + n]; }
        d_Bh[c * 8192 + i] = packh2(lo, hi);
    }
}

// ---------------- fused iteration kernel (256 threads, 2 CTAs/SM, 64-row tile) ----------------
// byte offsets
#define OB_AH1 17408
#define OB_AH2 34816
#define OB_HH  52224
#define OB_B   69632      // 4 groups x (2 x 4KB)
#define OB_BT  102400
#define OB_BIH 103936
#define OB_BHH 105472
#define OB_CNT 107008
#define OB_INV 107776
#define SMEM_IT 108032

__global__ __launch_bounds__(256, 2) void iter_kernel(int dir,
                                                      const float* __restrict__ bih,
                                                      const float* __restrict__ bhh,
                                                      const float* __restrict__ bt) {
    extern __shared__ unsigned char smraw[];
    const unsigned* hhin  = dir ? d_hhB : d_hhA;
    unsigned*       hhout = dir ? d_hhA : d_hhB;
    unsigned* AH0 = (unsigned*)(smraw);
    unsigned* AH1 = (unsigned*)(smraw + OB_AH1);
    unsigned* AH2 = (unsigned*)(smraw + OB_AH2);
    unsigned* HH  = (unsigned*)(smraw + OB_HH);
    float* sbt  = (float*)(smraw + OB_BT);
    float* sbih = (float*)(smraw + OB_BIH);
    float* sbhh = (float*)(smraw + OB_BHH);
    float* scnt = (float*)(smraw + OB_CNT);   // cnt_t * invden (3*64)
    float* sinv = (float*)(smraw + OB_INV);

    int tid = threadIdx.x, lane = tid & 31, wid = tid >> 5;   // wid 0..7
    int g = lane >> 2, tig = lane & 3;
    int r0 = (wid & 1) * 32, c0 = (wid >> 1) * 32;            // 2x4 grid of 32x32 tiles
    int cg = wid >> 1;                                        // column group 0..3
    int gtid = tid & 63;                                      // thread id within group
    int tile0 = blockIdx.x * 64;

    unsigned* B0v = (unsigned*)(smraw + OB_B + cg * 8192);
    unsigned* B1v = (unsigned*)(smraw + OB_B + cg * 8192 + 4096);
    unsigned b0a = (unsigned)__cvta_generic_to_shared(B0v);
    unsigned b1a = (unsigned)__cvta_generic_to_shared(B1v);

    // kick off first two half-chunks (group-local); they land during the gather
    PREF_G(b0a, 0, 0);
    PREF_G(b1a, 0, 1);

    for (int i = tid; i < 384; i += 256) { sbt[i] = bt[i]; sbih[i] = bih[i]; sbhh[i] = bhh[i]; }
    if (tid < 64) {
        int v = tile0 + tid;
        bool ok = v < NN;
        float inv = ok ? d_invden[v] : 0.f;
        sinv[tid]       = inv;
        scnt[tid]       = ok ? d_cntT[v] * inv : 0.f;
        scnt[64 + tid]  = ok ? d_cntT[NN + v] * inv : 0.f;
        scnt[128 + tid] = ok ? d_cntT[2 * NN + v] * inv : 0.f;
    }
    // stage h_prev fp16 tile from the packed state
    for (int it = 0; it < 8; it++) {
        int i = it * 256 + tid, r = i >> 5, q = i & 31, v = tile0 + r;
        uint2 val = (v < NN) ? *(const uint2*)&hhin[v * 64 + q * 2] : make_uint2(0u, 0u);
        *(uint2*)&HH[r * APW + q * 2] = val;
    }
    __syncthreads();   // sinv/scnt/biases visible before gather uses them

    // ---- CSR gather (fp16 inputs, fp32 accum, MLP=8): A_t[r] = inv * sum h*gate ----
    for (int r = wid; r < 64; r += 8) {
        int v = tile0 + r;
        float4 a0 = make_float4(0.f, 0.f, 0.f, 0.f), a1 = a0, a2 = a0;
        if (v < NN) {
            int st = d_rowp[v], dg = d_degi[v];
            for (int e = 0; e < dg; e += 8) {
                int m = dg - e;
                unsigned wd[8];
                uint2 hv[8], gv[8];
#pragma unroll
                for (int i = 0; i < 8; i++)
                    wd[i] = (i < m) ? d_epk[st + e + i] : 0xFFFFFFFFu;
#pragma unroll
                for (int i = 0; i < 8; i++) {
                    if (wd[i] != 0xFFFFFFFFu) {
                        int s = wd[i] & 0x1FFFF, p = (wd[i] >> 17) & 0x3FF;
                        hv[i] = *(const uint2*)&hhin[s * 64 + lane * 2];
                        gv[i] = *(const uint2*)&d_gh[p * 64 + lane * 2];
                    }
                }
#pragma unroll
                for (int i = 0; i < 8; i++) {
                    if (wd[i] != 0xFFFFFFFFu) {
                        int t = wd[i] >> 27;
                        float2 h0f = unph2(hv[i].x), h1f = unph2(hv[i].y);
                        float2 g0f = unph2(gv[i].x), g1f = unph2(gv[i].y);
                        float4 mv;
                        mv.x = h0f.x * g0f.x; mv.y = h0f.y * g0f.y;
                        mv.z = h1f.x * g1f.x; mv.w = h1f.y * g1f.y;
                        if (t == 0) { a0.x += mv.x; a0.y += mv.y; a0.z += mv.z; a0.w += mv.w; }
                        else if (t == 1) { a1.x += mv.x; a1.y += mv.y; a1.z += mv.z; a1.w += mv.w; }
                        else { a2.x += mv.x; a2.y += mv.y; a2.z += mv.z; a2.w += mv.w; }
                    }
                }
            }
            float iv = sinv[r];
            a0.x *= iv; a0.y *= iv; a0.z *= iv; a0.w *= iv;
            a1.x *= iv; a1.y *= iv; a1.z *= iv; a1.w *= iv;
            a2.x *= iv; a2.y *= iv; a2.z *= iv; a2.w *= iv;
        }
        uint2 o;
        o.x = packh2(a0.x, a0.y); o.y = packh2(a0.z, a0.w);
        *(uint2*)&AH0[r * APW + lane * 2] = o;
        o.x = packh2(a1.x, a1.y); o.y = packh2(a1.z, a1.w);
        *(uint2*)&AH1[r * APW + lane * 2] = o;
        o.x = packh2(a2.x, a2.y); o.y = packh2(a2.z, a2.w);
        *(uint2*)&AH2[r * APW + lane * 2] = o;
    }
    __syncthreads();   // A tiles ready for all groups

    float acc[4][8];

    // ---- stage 1: acc = sum_t A_t @ Wt[t] ----  (chunks 0,1,2 as halves)
    ZACCT(acc);
    GSTEP(B0v, AH0, 0, b0a, 1, 0);
    GSTEP(B1v, AH0, 4, b1a, 1, 1);
    GSTEP(B0v, AH1, 0, b0a, 2, 0);
    GSTEP(B1v, AH1, 4, b1a, 2, 1);
    GSTEP(B0v, AH2, 0, b0a, 3, 0);
    GSTEP(B1v, AH2, 4, b1a, 3, 1);
    __syncthreads();   // all groups done reading AH0/AH1/AH2

    // epilogue: agg = acc + sum_t (cnt_t*inv)*bt_t  -> AH0 (fp16)
#pragma unroll
    for (int nt = 0; nt < 4; nt++)
#pragma unroll
        for (int q = 0; q < 4; q++) {
            int row = r0 + g + q * 8;
            int colb = c0 + nt * 8 + 2 * tig;
            float v0 = acc[nt][q * 2 + 0] + scnt[row] * sbt[colb] +
                       scnt[64 + row] * sbt[128 + colb] + scnt[128 + row] * sbt[256 + colb];
            float v1 = acc[nt][q * 2 + 1] + scnt[row] * sbt[colb + 1] +
                       scnt[64 + row] * sbt[128 + colb + 1] + scnt[128 + row] * sbt[256 + colb + 1];
            AH0[row * APW + (colb >> 1)] = packh2(v0, v1);
        }
    __syncthreads();   // agg tile visible to all groups

    // ---- stage 2: GRU ----
    float rr[4][8];

    // r = sigma(agg@Wih_r + h@Whh_r + b)    (chunks 3, 6)
    ZACCT(acc);
    GSTEP(B0v, AH0, 0, b0a, 6, 0);
    GSTEP(B1v, AH0, 4, b1a, 6, 1);
    GSTEP(B0v, HH,  0, b0a, 8, 0);
    GSTEP(B1v, HH,  4, b1a, 8, 1);
#pragma unroll
    for (int nt = 0; nt < 4; nt++)
#pragma unroll
        for (int i = 0; i < 8; i++) {
            int col = c0 + nt * 8 + 2 * tig + (i & 1);
            rr[nt][i] = fsig(acc[nt][i] + sbih[col] + sbhh[col]);
        }

    // rghn = r * (h@Whh_n + bhh_n)          (chunk 8)
    ZACCT(acc);
    GSTEP(B0v, HH, 0, b0a, 5, 0);
    GSTEP(B1v, HH, 4, b1a, 5, 1);
#pragma unroll
    for (int nt = 0; nt < 4; nt++)
#pragma unroll
        for (int i = 0; i < 8; i++) {
            int col = c0 + nt * 8 + 2 * tig + (i & 1);
            rr[nt][i] = rr[nt][i] * (acc[nt][i] + sbhh[256 + col]);
        }

    // n = tanh(agg@Wih_n + bih_n + rghn)    (chunk 5)
    ZACCT(acc);
    GSTEP(B0v, AH0, 0, b0a, 4, 0);
    GSTEP(B1v, AH0, 4, b1a, 4, 1);
#pragma unroll
    for (int nt = 0; nt < 4; nt++)
#pragma unroll
        for (int i = 0; i < 8; i++) {
            int col = c0 + nt * 8 + 2 * tig + (i & 1);
            rr[nt][i] = ftanh(acc[nt][i] + sbih[256 + col] + rr[nt][i]);
        }

    // z = sigma(agg@Wih_z + h@Whh_z + b);  h_new = (1-z)*n + z*h_prev   (chunks 4, 7)
    ZACCT(acc);
    GSTEP(B0v, AH0, 0, b0a, 7, 0);
    GSTEP(B1v, AH0, 4, b1a, 7, 1);
    GSTEP_NP(B0v, HH, 0, 1);
    GSTEP_NP(B1v, HH, 4, 0);
#pragma unroll
    for (int nt = 0; nt < 4; nt++)
#pragma unroll
        for (int q = 0; q < 4; q++) {
            int row = r0 + g + q * 8;
            int v = tile0 + row;
            if (v < NN) {
                int colb = c0 + nt * 8 + 2 * tig;
                float z0 = fsig(acc[nt][q * 2 + 0] + sbih[128 + colb] + sbhh[128 + colb]);
                float z1 = fsig(acc[nt][q * 2 + 1] + sbih[129 + colb] + sbhh[129 + colb]);
                float2 hp = unph2(HH[row * APW + (colb >> 1)]);   // h_prev from smem tile
                float o0 = (1.f - z0) * rr[nt][q * 2 + 0] + z0 * hp.x;
                float o1 = (1.f - z1) * rr[nt][q * 2 + 1] + z1 * hp.y;
                hhout[v * 64 + (colb >> 1)] = packh2(o0, o1);
            }
        }
}

// ---------------- readout (256 threads, 64-row tiles) ----------------
#define RB_H0  17408
#define RB_BS  34816
#define RB_B1  67584
#define RB_W2  68096
#define RB_RED 68608
#define SMEM_RO 69120

__global__ __launch_bounds__(256, 2) void readout_tc(const float* __restrict__ b1,
                                                     const float* __restrict__ W2,
                                                     const float* __restrict__ b2,
                                                     float* __restrict__ out) {
    extern __shared__ unsigned char smraw[];
    unsigned* HA  = (unsigned*)(smraw);
    unsigned* H0  = (unsigned*)(smraw + RB_H0);
    unsigned* Bs  = (unsigned*)(smraw + RB_BS);
    float* sb1  = (float*)(smraw + RB_B1);
    float* sW2  = (float*)(smraw + RB_W2);
    float* sred = (float*)(smraw + RB_RED);

    int tid = threadIdx.x, lane = tid & 31, wid = tid >> 5;
    int g = lane >> 2, tig = lane & 3;
    int r0 = (wid & 3) * 16, c0 = (wid >> 2) * 64;
    int tile0 = blockIdx.x * 64;

    if (tid < 128) { sb1[tid] = b1[tid]; sW2[tid] = W2[tid]; sred[tid] = 0.f; }
    for (int it = 0; it < 8; it++) {
        int i = it * 256 + tid, r = i >> 5, q = i & 31, v = tile0 + r;
        uint2 h  = (v < NN) ? *(const uint2*)&d_hhA[v * 64 + q * 2] : make_uint2(0u, 0u);
        uint2 h0 = (v < NN) ? *(const uint2*)&d_h0h[v * 64 + q * 2] : make_uint2(0u, 0u);
        *(uint2*)&HA[r * APW + q * 2] = h;
        *(uint2*)&H0[r * APW + q * 2] = h0;
    }

    float acc[8][4];
    ZACC4(acc);
    STAGE_B256(Bs, 9);  gemm_h(HA, Bs, r0, c0, g, tig, acc);
    STAGE_B256(Bs, 10); gemm_h(H0, Bs, r0, c0, g, tig, acc);

    float p0 = 0.f, p1 = 0.f;
#pragma unroll
    for (int nt = 0; nt < 8; nt++) {
        int colb = c0 + nt * 8 + 2 * tig;
        p0 += fmaxf(acc[nt][0] + sb1[colb],     0.f) * sW2[colb];
        p0 += fmaxf(acc[nt][1] + sb1[colb + 1], 0.f) * sW2[colb + 1];
        p1 += fmaxf(acc[nt][2] + sb1[colb],     0.f) * sW2[colb];
        p1 += fmaxf(acc[nt][3] + sb1[colb + 1], 0.f) * sW2[colb + 1];
    }
    p0 += __shfl_down_sync(0xffffffffu, p0, 1, 4);
    p0 += __shfl_down_sync(0xffffffffu, p0, 2, 4);
    p1 += __shfl_down_sync(0xffffffffu, p1, 1, 4);
    p1 += __shfl_down_sync(0xffffffffu, p1, 2, 4);
    if (tig == 0) {
        int wn = wid >> 2;
        sred[wn * 64 + r0 + g]     = p0;
        sred[wn * 64 + r0 + g + 8] = p1;
    }
    __syncthreads();
    if (tid < 64) {
        int v = tile0 + tid;
        if (v < NN) out[v] = sred[tid] + sred[64 + tid] + b2[0];
    }
}

// ---------------- launch ----------------
extern "C" void kernel_launch(void* const* d_in, const int* in_sizes, int n_in,
                              void* d_out, int out_size) {
    const int*   xidx    = (const int*)d_in[0];
    const float* sel     = (const float*)d_in[1];
    const int*   eidx    = (const int*)d_in[2];
    const int*   etype   = (const int*)d_in[3];
    const int*   epos    = (const int*)d_in[4];
    const float* emb     = (const float*)d_in[5];
    const float* pos_enc = (const float*)d_in[6];
    const float* Wg      = (const float*)d_in[7];
    const float* bg      = (const float*)d_in[8];
    const float* Wt      = (const float*)d_in[9];
    const float* bt      = (const float*)d_in[10];
    const float* Wih     = (const float*)d_in[11];
    const float* Whh     = (const float*)d_in[12];
    const float* bih     = (const float*)d_in[13];
    const float* bhh     = (const float*)d_in[14];
    const float* W1      = (const float*)d_in[15];
    const float* b1      = (const float*)d_in[16];
    const float* W2      = (const float*)d_in[17];
    const float* b2      = (const float*)d_in[18];
    const int* src = eidx;
    const int* dst = eidx + EE;
    float* out = (float*)d_out;

    cudaFuncSetAttribute(iter_kernel, cudaFuncAttributeMaxDynamicSharedMemorySize, SMEM_IT);
    cudaFuncSetAttribute(readout_tc, cudaFuncAttributeMaxDynamicSharedMemorySize, SMEM_RO);

    gate_kernel<<<NPOS, 64>>>(pos_enc, Wg, bg);
    init_h<<<NN, HD>>>(xidx, sel, emb);
    zero_misc<<<(NT * NN + 255) / 256, 256>>>();
    cnt_kernel<<<(EE + 255) / 256, 256>>>(dst, etype);
    invden_kernel<<<(NN + 255) / 256, 256>>>();
    scanA<<<98, 1024>>>();
    scanB<<<1, 32>>>();
    scanC<<<(NN + 255) / 256, 256>>>();
    fill_kernel<<<(EE + 255) / 256, 256>>>(src, dst, etype, epos);
    bprep<<<11, 256>>>(Wt, Wih, Whh, W1);

    for (int it = 0; it < 6; it++)
        iter_kernel<<<NT64, 256, SMEM_IT>>>(it & 1, bih, bhh, bt);

    readout_tc<<<NT64, 256, SMEM_RO>>>(b1, W2, b2, out);
}

// round 17
// speedup vs baseline: 1.0242x; 1.0242x over previous
#include <cuda_runtime.h>
#include <cuda_fp16.h>
#include <cstdint>

#define NN   100000
#define EE   640000
#define HD   128
#define NT   3
#define PD   64
#define NPOS 513
#define VEMB 96
#define NT64  1563         // ceil(100000/64)
#define APW  68            // A/H tile pitch in 4B words (136 halves)

// ---------------- device scratch ----------------
static __device__ unsigned d_hhA[NN * 64];    // fp16 h state (half2-packed), ping
static __device__ unsigned d_hhB[NN * 64];    // fp16 h state, pong
static __device__ unsigned d_h0h[NN * 64];    // fp16 h0 (half2-packed)
static __device__ unsigned d_gh[NPOS * 64];   // fp16 gate table (half2-packed)
static __device__ float d_cntT[NT * NN];
static __device__ float d_invden[NN];
static __device__ int   d_degi[NN];
static __device__ int   d_fill[NN];
static __device__ int   d_rowtmp[NN];
static __device__ int   d_rowp[NN];
static __device__ int   d_bsum[98];
static __device__ unsigned d_epk[EE];
static __device__ __align__(16) unsigned d_Bh[11 * 8192];  // fp16 weight chunks (32KB each)

// ---------------- helpers ----------------
__device__ __forceinline__ float fsig(float x) {
    return __fdividef(1.0f, 1.0f + __expf(-x));
}
__device__ __forceinline__ float ftanh(float x) {
    return 1.0f - __fdividef(2.0f, __expf(2.0f * x) + 1.0f);
}
__device__ __forceinline__ unsigned packh2(float lo, float hi) {
    __half2 h = __floats2half2_rn(lo, hi);
    return *(unsigned*)&h;
}
__device__ __forceinline__ float2 unph2(unsigned u) {
    return __half22float2(*(__half2*)&u);
}

#define MMA16(acc0, acc1, acc2, acc3, a0, a1, a2, a3, bx, by)                    \
    asm volatile("mma.sync.aligned.m16n8k16.row.col.f32.f16.f16.f32 "            \
                 "{%0,%1,%2,%3}, {%4,%5,%6,%7}, {%8,%9}, {%0,%1,%2,%3};"         \
                 : "+f"(acc0), "+f"(acc1), "+f"(acc2), "+f"(acc3)                \
                 : "r"(a0), "r"(a1), "r"(a2), "r"(a3), "r"(bx), "r"(by))

// 32x32 warp tile over HALF a K-chunk (4 k-steps): acc[4][8]
__device__ __forceinline__ void gemm_half(const unsigned* __restrict__ Aw,
                                          const unsigned* __restrict__ Bs,
                                          int ksb, int r0, int c0, int g, int tig,
                                          float acc[4][8]) {
#pragma unroll
    for (int ks = 0; ks < 4; ks++) {
        const unsigned* ap = Aw + (r0 + g) * APW + (ksb + ks) * 8 + tig;
        unsigned a0 = ap[0],            a1 = ap[8 * APW],
                 a2 = ap[4],            a3 = ap[8 * APW + 4];
        unsigned a4 = ap[16 * APW],     a5 = ap[24 * APW],
                 a6 = ap[16 * APW + 4], a7 = ap[24 * APW + 4];
        const uint2* bp = (const uint2*)Bs + ks * 512 + (c0 + g) * 4 + tig;
#pragma unroll
        for (int nt = 0; nt < 4; nt++) {
            uint2 b = bp[nt * 32];
            MMA16(acc[nt][0], acc[nt][1], acc[nt][2], acc[nt][3],
                  a0, a1, a2, a3, b.x, b.y);
            MMA16(acc[nt][4], acc[nt][5], acc[nt][6], acc[nt][7],
                  a4, a5, a6, a7, b.x, b.y);
        }
    }
}

#define ZACCT(acc) do { _Pragma("unroll") for (int _n = 0; _n < 4; _n++) \
    _Pragma("unroll") for (int _i = 0; _i < 8; _i++) acc[_n][_i]=0.f; } while (0)

// cp.async prefetch of one 16KB HALF-chunk by 256 threads (4 x 16B each)
#define PREF_H(saddr, ch, hf) do {                                                \
    const char* _g = (const char*)d_Bh + (ch) * 32768 + (hf) * 16384;             \
    _Pragma("unroll") for (int _k = 0; _k < 4; _k++) {                            \
        int _off = (tid + 256 * _k) * 16;                                         \
        asm volatile("cp.async.cg.shared.global [%0], [%1], 16;"                  \
                     :: "r"((saddr) + _off), "l"(_g + _off));                     \
    }                                                                             \
    asm volatile("cp.async.commit_group;" ::: "memory");                          \
} while (0)
#define CP_WAIT(n) asm volatile("cp.async.wait_group %0;" :: "n"(n) : "memory")

// pipeline step: wait current half, mma, release buffer, prefetch half 2 ahead
#define HSTEP(bufv, Aw, ksb, bufa, pch, phf) do {                                 \
    CP_WAIT(1); __syncthreads();                                                  \
    gemm_half(Aw, bufv, ksb, r0, c0, g, tig, acc);                                \
    __syncthreads();                                                              \
    PREF_H(bufa, pch, phf); } while (0)
#define HSTEP_NP(bufv, Aw, ksb, wn) do {                                          \
    CP_WAIT(wn); __syncthreads();                                                 \
    gemm_half(Aw, bufv, ksb, r0, c0, g, tig, acc); } while (0)

// ---------------- prep kernels ----------------
__global__ void gate_kernel(const float* __restrict__ pos_enc, const float* __restrict__ Wg,
                            const float* __restrict__ bg) {
    int p = blockIdx.x, j = threadIdx.x;   // j in [0,64)
    __shared__ float pe[PD];
    pe[j] = pos_enc[p * PD + j];
    __syncthreads();
    float a0 = bg[2 * j], a1 = bg[2 * j + 1];
#pragma unroll
    for (int k = 0; k < PD; k++) {
        float w = pe[k];
        a0 = fmaf(w, Wg[k * HD + 2 * j], a0);
        a1 = fmaf(w, Wg[k * HD + 2 * j + 1], a1);
    }
    d_gh[p * 64 + j] = packh2(2.0f / (1.0f + expf(-a0)), 2.0f / (1.0f + expf(-a1)));
}

__global__ void init_h(const int* __restrict__ xidx, const float* __restrict__ sel,
                       const float* __restrict__ emb) {
    int v = blockIdx.x, j = threadIdx.x;
    float val = (j < VEMB) ? emb[xidx[v] * VEMB + j] : sel[v * 32 + (j - VEMB)];
    float nb = __shfl_down_sync(0xffffffffu, val, 1);
    if (!(j & 1)) {
        unsigned pk = packh2(val, nb);
        d_hhA[v * 64 + (j >> 1)] = pk;
        d_h0h[v * 64 + (j >> 1)] = pk;
    }
}

__global__ void zero_misc() {
    int i = blockIdx.x * blockDim.x + threadIdx.x;
    if (i < NT * NN) d_cntT[i] = 0.0f;
    if (i < NN) { d_degi[i] = 0; d_fill[i] = 0; }
}
__global__ void cnt_kernel(const int* __restrict__ dst, const int* __restrict__ etype) {
    int e = blockIdx.x * blockDim.x + threadIdx.x;
    if (e < EE) {
        atomicAdd(&d_cntT[etype[e] * NN + dst[e]], 1.0f);
        atomicAdd(&d_degi[dst[e]], 1);
    }
}

__global__ void scanA() {
    __shared__ int s[1024];
    int b = blockIdx.x, t = threadIdx.x;
    int i = b * 1024 + t;
    s[t] = (i < NN) ? d_degi[i] : 0;
    __syncthreads();
#pragma unroll
    for (int off = 1; off < 1024; off <<= 1) {
        int x = (t >= off) ? s[t - off] : 0;
        __syncthreads();
        s[t] += x;
        __syncthreads();
    }
    if (i < NN) d_rowtmp[i] = s[t];
    if (t == 1023) d_bsum[b] = s[1023];
}
__global__ void scanB() {
    if (threadIdx.x == 0) {
        int run = 0;
        for (int b = 0; b < 98; b++) { int x = d_bsum[b]; d_bsum[b] = run; run += x; }
    }
}
__global__ void scanC() {   // row pointers + invden (merged)
    int i = blockIdx.x * blockDim.x + threadIdx.x;
    if (i < NN) {
        int dg = d_degi[i];
        d_rowp[i] = d_rowtmp[i] - dg + d_bsum[i >> 10];
        d_invden[i] = 1.0f / fmaxf((float)dg, 1.0f);
    }
}
__global__ void fill_kernel(const int* __restrict__ src, const int* __restrict__ dst,
                            const int* __restrict__ etype, const int* __restrict__ epos) {
    int e = blockIdx.x * blockDim.x + threadIdx.x;
    if (e < EE) {
        int dv = dst[e];
        int slot = d_rowp[dv] + atomicAdd(&d_fill[dv], 1);
        d_epk[slot] = (unsigned)src[e] | ((unsigned)epos[e] << 17) | ((unsigned)etype[e] << 27);
    }
}

// chunks: 0..2 Wt[t] (B[k][n]=Wt[t][k][n]); 3..5 Wih r/z/n (B[k][o]=Wih[o][k]);
//         6..8 Whh r/z/n; 9..10 W1 halves
__global__ void bprep(const float* __restrict__ Wt, const float* __restrict__ Wih,
                      const float* __restrict__ Whh, const float* __restrict__ W1) {
    int c = blockIdx.x;
    for (int i = threadIdx.x; i < 8192; i += blockDim.x) {
        int j = i & 1, tig = (i >> 1) & 3, n = (i >> 3) & 127, ks = i >> 10;
        int k0 = ks * 16 + j * 8 + tig * 2;
        float lo, hi;
        if (c < 3)       { lo = Wt[c * 16384 + k0 * HD + n];        hi = Wt[c * 16384 + (k0 + 1) * HD + n]; }
        else if (c < 6)  { lo = Wih[((c - 3) * 128 + n) * HD + k0]; hi = Wih[((c - 3) * 128 + n) * HD + k0 + 1]; }
        else if (c < 9)  { lo = Whh[((c - 6) * 128 + n) * HD + k0]; hi = Whh[((c - 6) * 128 + n) * HD + k0 + 1]; }
        else if (c == 9) { lo = W1[k0 * HD + n];                    hi = W1[(k0 + 1) * HD + n]; }
        else             { lo = W1[(128 + k0) * HD + n];            hi = W1[(129 + k0) * HD + n]; }
        d_Bh[c * 8192 + i] = packh2(lo, hi);
    }
}

// ---------------- fused iteration kernel (256 threads, 2 CTAs/SM, 64-row tile) ----------------
// byte offsets
#define OB_AH1 17408
#define OB_AH2 34816
#define OB_HH  52224
#define OB_B0  69632
#define OB_B1  86016
#define OB_BT  102400
#define OB_BIH 103936
#define OB_BHH 105472
#define OB_CNT 107008
#define OB_INV 107776
#define SMEM_IT 108032
// readout scratch (reuses dead B0 region after final gemms)
#define RO_B1  (OB_B0)
#define RO_W2  (OB_B0 + 512)
#define RO_RED (OB_B0 + 1024)

__global__ __launch_bounds__(256, 2) void iter_kernel(int dir, int last,
                                                      const float* __restrict__ bih,
                                                      const float* __restrict__ bhh,
                                                      const float* __restrict__ bt,
                                                      const float* __restrict__ b1,
                                                      const float* __restrict__ W2,
                                                      const float* __restrict__ b2,
                                                      float* __restrict__ out) {
    extern __shared__ unsigned char smraw[];
    const unsigned* hhin  = dir ? d_hhB : d_hhA;
    unsigned*       hhout = dir ? d_hhA : d_hhB;
    unsigned* AH0 = (unsigned*)(smraw);
    unsigned* AH1 = (unsigned*)(smraw + OB_AH1);
    unsigned* AH2 = (unsigned*)(smraw + OB_AH2);
    unsigned* HH  = (unsigned*)(smraw + OB_HH);
    unsigned* B0v = (unsigned*)(smraw + OB_B0);
    unsigned* B1v = (unsigned*)(smraw + OB_B1);
    float* sbt  = (float*)(smraw + OB_BT);
    float* sbih = (float*)(smraw + OB_BIH);
    float* sbhh = (float*)(smraw + OB_BHH);
    float* scnt = (float*)(smraw + OB_CNT);   // cnt_t * invden (3*64)
    float* sinv = (float*)(smraw + OB_INV);

    int tid = threadIdx.x, lane = tid & 31, wid = tid >> 5;   // wid 0..7
    int g = lane >> 2, tig = lane & 3;
    int r0 = (wid & 1) * 32, c0 = (wid >> 1) * 32;            // 2x4 grid of 32x32 tiles
    int tile0 = blockIdx.x * 64;

    unsigned b0a = (unsigned)__cvta_generic_to_shared(B0v);
    unsigned b1a = (unsigned)__cvta_generic_to_shared(B1v);

    // kick off first two half-chunks; they land during the gather
    PREF_H(b0a, 0, 0);
    PREF_H(b1a, 0, 1);

    for (int i = tid; i < 384; i += 256) { sbt[i] = bt[i]; sbih[i] = bih[i]; sbhh[i] = bhh[i]; }
    if (tid < 64) {
        int v = tile0 + tid;
        bool ok = v < NN;
        float inv = ok ? d_invden[v] : 0.f;
        sinv[tid]       = inv;
        scnt[tid]       = ok ? d_cntT[v] * inv : 0.f;
        scnt[64 + tid]  = ok ? d_cntT[NN + v] * inv : 0.f;
        scnt[128 + tid] = ok ? d_cntT[2 * NN + v] * inv : 0.f;
    }
    // stage h_prev fp16 tile from the packed state
    for (int it = 0; it < 8; it++) {
        int i = it * 256 + tid, r = i >> 5, q = i & 31, v = tile0 + r;
        uint2 val = (v < NN) ? *(const uint2*)&hhin[v * 64 + q * 2] : make_uint2(0u, 0u);
        *(uint2*)&HH[r * APW + q * 2] = val;
    }
    __syncthreads();   // sinv/scnt/biases visible before gather uses them

    // ---- CSR gather (fp16 inputs, fp32 accum, MLP=8): A_t[r] = inv * sum h*gate ----
    for (int r = wid; r < 64; r += 8) {
        int v = tile0 + r;
        float4 a0 = make_float4(0.f, 0.f, 0.f, 0.f), a1 = a0, a2 = a0;
        if (v < NN) {
            int st = d_rowp[v], dg = d_degi[v];
            for (int e = 0; e < dg; e += 8) {
                int m = dg - e;
                unsigned wd[8];
                uint2 hv[8], gv[8];
#pragma unroll
                for (int i = 0; i < 8; i++)
                    wd[i] = (i < m) ? d_epk[st + e + i] : 0xFFFFFFFFu;
#pragma unroll
                for (int i = 0; i < 8; i++) {
                    if (wd[i] != 0xFFFFFFFFu) {
                        int s = wd[i] & 0x1FFFF, p = (wd[i] >> 17) & 0x3FF;
                        hv[i] = *(const uint2*)&hhin[s * 64 + lane * 2];
                        gv[i] = *(const uint2*)&d_gh[p * 64 + lane * 2];
                    }
                }
#pragma unroll
                for (int i = 0; i < 8; i++) {
                    if (wd[i] != 0xFFFFFFFFu) {
                        int t = wd[i] >> 27;
                        float2 h0f = unph2(hv[i].x), h1f = unph2(hv[i].y);
                        float2 g0f = unph2(gv[i].x), g1f = unph2(gv[i].y);
                        float4 mv;
                        mv.x = h0f.x * g0f.x; mv.y = h0f.y * g0f.y;
                        mv.z = h1f.x * g1f.x; mv.w = h1f.y * g1f.y;
                        if (t == 0) { a0.x += mv.x; a0.y += mv.y; a0.z += mv.z; a0.w += mv.w; }
                        else if (t == 1) { a1.x += mv.x; a1.y += mv.y; a1.z += mv.z; a1.w += mv.w; }
                        else { a2.x += mv.x; a2.y += mv.y; a2.z += mv.z; a2.w += mv.w; }
                    }
                }
            }
            float iv = sinv[r];
            a0.x *= iv; a0.y *= iv; a0.z *= iv; a0.w *= iv;
            a1.x *= iv; a1.y *= iv; a1.z *= iv; a1.w *= iv;
            a2.x *= iv; a2.y *= iv; a2.z *= iv; a2.w *= iv;
        }
        uint2 o;
        o.x = packh2(a0.x, a0.y); o.y = packh2(a0.z, a0.w);
        *(uint2*)&AH0[r * APW + lane * 2] = o;
        o.x = packh2(a1.x, a1.y); o.y = packh2(a1.z, a1.w);
        *(uint2*)&AH1[r * APW + lane * 2] = o;
        o.x = packh2(a2.x, a2.y); o.y = packh2(a2.z, a2.w);
        *(uint2*)&AH2[r * APW + lane * 2] = o;
    }

    float acc[4][8];

    // ---- stage 1: acc = sum_t A_t @ Wt[t] ----  (chunks 0,1,2 as halves)
    ZACCT(acc);
    HSTEP(B0v, AH0, 0, b0a, 1, 0);
    HSTEP(B1v, AH0, 4, b1a, 1, 1);
    HSTEP(B0v, AH1, 0, b0a, 2, 0);
    HSTEP(B1v, AH1, 4, b1a, 2, 1);
    HSTEP(B0v, AH2, 0, b0a, 3, 0);
    HSTEP(B1v, AH2, 4, b1a, 3, 1);

    // epilogue: agg = acc + sum_t (cnt_t*inv)*bt_t  -> AH0 (fp16)
#pragma unroll
    for (int nt = 0; nt < 4; nt++)
#pragma unroll
        for (int q = 0; q < 4; q++) {
            int row = r0 + g + q * 8;
            int colb = c0 + nt * 8 + 2 * tig;
            float v0 = acc[nt][q * 2 + 0] + scnt[row] * sbt[colb] +
                       scnt[64 + row] * sbt[128 + colb] + scnt[128 + row] * sbt[256 + colb];
            float v1 = acc[nt][q * 2 + 1] + scnt[row] * sbt[colb + 1] +
                       scnt[64 + row] * sbt[128 + colb + 1] + scnt[128 + row] * sbt[256 + colb + 1];
            AH0[row * APW + (colb >> 1)] = packh2(v0, v1);
        }

    // ---- stage 2: GRU ----
    float rr[4][8];

    // r = sigma(agg@Wih_r + h@Whh_r + b)    (chunks 3, 6)
    ZACCT(acc);
    HSTEP(B0v, AH0, 0, b0a, 6, 0);
    HSTEP(B1v, AH0, 4, b1a, 6, 1);
    HSTEP(B0v, HH,  0, b0a, 8, 0);
    HSTEP(B1v, HH,  4, b1a, 8, 1);
#pragma unroll
    for (int nt = 0; nt < 4; nt++)
#pragma unroll
        for (int i = 0; i < 8; i++) {
            int col = c0 + nt * 8 + 2 * tig + (i & 1);
            rr[nt][i] = fsig(acc[nt][i] + sbih[col] + sbhh[col]);
        }

    // rghn = r * (h@Whh_n + bhh_n)          (chunk 8)
    ZACCT(acc);
    HSTEP(B0v, HH, 0, b0a, 5, 0);
    HSTEP(B1v, HH, 4, b1a, 5, 1);
#pragma unroll
    for (int nt = 0; nt < 4; nt++)
#pragma unroll
        for (int i = 0; i < 8; i++) {
            int col = c0 + nt * 8 + 2 * tig + (i & 1);
            rr[nt][i] = rr[nt][i] * (acc[nt][i] + sbhh[256 + col]);
        }

    // n = tanh(agg@Wih_n + bih_n + rghn)    (chunk 5)
    ZACCT(acc);
    HSTEP(B0v, AH0, 0, b0a, 4, 0);
    HSTEP(B1v, AH0, 4, b1a, 4, 1);
#pragma unroll
    for (int nt = 0; nt < 4; nt++)
#pragma unroll
        for (int i = 0; i < 8; i++) {
            int col = c0 + nt * 8 + 2 * tig + (i & 1);
            rr[nt][i] = ftanh(acc[nt][i] + sbih[256 + col] + rr[nt][i]);
        }

    // z = sigma(agg@Wih_z + h@Whh_z + b);  h_new = (1-z)*n + z*h_prev   (chunks 4, 7)
    ZACCT(acc);
    HSTEP(B0v, AH0, 0, b0a, 7, 0);
    HSTEP(B1v, AH0, 4, b1a, 7, 1);
    if (last) {
        // keep pipeline alive: prefetch W1 chunk 9 halves during the z GEMMs
        HSTEP(B0v, HH, 0, b0a, 9, 0);
        HSTEP(B1v, HH, 4, b1a, 9, 1);
        // (trailing sync of the 2nd HSTEP orders all HH reads before the writes below)
    } else {
        HSTEP_NP(B0v, HH, 0, 1);
        HSTEP_NP(B1v, HH, 4, 0);
    }
#pragma unroll
    for (int nt = 0; nt < 4; nt++)
#pragma unroll
        for (int q = 0; q < 4; q++) {
            int row = r0 + g + q * 8;
            int v = tile0 + row;
            if (v < NN) {
                int colb = c0 + nt * 8 + 2 * tig;
                float z0 = fsig(acc[nt][q * 2 + 0] + sbih[128 + colb] + sbhh[128 + colb]);
                float z1 = fsig(acc[nt][q * 2 + 1] + sbih[129 + colb] + sbhh[129 + colb]);
                float2 hp = unph2(HH[row * APW + (colb >> 1)]);   // h_prev from smem tile
                float o0 = (1.f - z0) * rr[nt][q * 2 + 0] + z0 * hp.x;
                float o1 = (1.f - z1) * rr[nt][q * 2 + 1] + z1 * hp.y;
                unsigned pk = packh2(o0, o1);
                hhout[v * 64 + (colb >> 1)] = pk;
                if (last) HH[row * APW + (colb >> 1)] = pk;   // h_new tile for readout
            }
        }

    if (!last) return;

    // ---- fused readout: logits = relu([h_new,h0]@W1 + b1)@W2 + b2 ----
    __syncthreads();   // h_new tile complete
    // stage h0 into dead AH1 tile
    for (int it = 0; it < 8; it++) {
        int i = it * 256 + tid, r = i >> 5, q = i & 31, v = tile0 + r;
        uint2 val = (v < NN) ? *(const uint2*)&d_h0h[v * 64 + q * 2] : make_uint2(0u, 0u);
        *(uint2*)&AH1[r * APW + q * 2] = val;
    }
    ZACCT(acc);
    HSTEP(B0v, HH, 0, b0a, 10, 0);   // c9h0 (W1 rows 0-63 pairs? = W1a half0), prefetch c10h0
    HSTEP(B1v, HH, 4, b1a, 10, 1);   // c9h1, prefetch c10h1
    HSTEP_NP(B0v, AH1, 0, 1);        // c10h0: h0 @ W1b half0
    HSTEP_NP(B1v, AH1, 4, 0);        // c10h1
    __syncthreads();                 // B0 region dead -> reuse for reduction scratch
    float* sb1r = (float*)(smraw + RO_B1);
    float* sW2r = (float*)(smraw + RO_W2);
    float* sred = (float*)(smraw + RO_RED);
    if (tid < 128) { sb1r[tid] = b1[tid]; sW2r[tid] = W2[tid]; }
    __syncthreads();

    float p[4] = {0.f, 0.f, 0.f, 0.f};
#pragma unroll
    for (int nt = 0; nt < 4; nt++)
#pragma unroll
        for (int q = 0; q < 4; q++) {
            int colb = c0 + nt * 8 + 2 * tig;
            p[q] += fmaxf(acc[nt][q * 2 + 0] + sb1r[colb],     0.f) * sW2r[colb]
                  + fmaxf(acc[nt][q * 2 + 1] + sb1r[colb + 1], 0.f) * sW2r[colb + 1];
        }
#pragma unroll
    for (int q = 0; q < 4; q++) {
        p[q] += __shfl_down_sync(0xffffffffu, p[q], 1, 4);
        p[q] += __shfl_down_sync(0xffffffffu, p[q], 2, 4);
    }
    if (tig == 0) {
        int cg = wid >> 1;
#pragma unroll
        for (int q = 0; q < 4; q++)
            sred[cg * 64 + r0 + g + q * 8] = p[q];
    }
    __syncthreads();
    if (tid < 64) {
        int v = tile0 + tid;
        if (v < NN)
            out[v] = sred[tid] + sred[64 + tid] + sred[128 + tid] + sred[192 + tid] + b2[0];
    }
}

// ---------------- launch ----------------
extern "C" void kernel_launch(void* const* d_in, const int* in_sizes, int n_in,
                              void* d_out, int out_size) {
    const int*   xidx    = (const int*)d_in[0];
    const float* sel     = (const float*)d_in[1];
    const int*   eidx    = (const int*)d_in[2];
    const int*   etype   = (const int*)d_in[3];
    const int*   epos    = (const int*)d_in[4];
    const float* emb     = (const float*)d_in[5];
    const float* pos_enc = (const float*)d_in[6];
    const float* Wg      = (const float*)d_in[7];
    const float* bg      = (const float*)d_in[8];
    const float* Wt      = (const float*)d_in[9];
    const float* bt      = (const float*)d_in[10];
    const float* Wih     = (const float*)d_in[11];
    const float* Whh     = (const float*)d_in[12];
    const float* bih     = (const float*)d_in[13];
    const float* bhh     = (const float*)d_in[14];
    const float* W1      = (const float*)d_in[15];
    const float* b1      = (const float*)d_in[16];
    const float* W2      = (const float*)d_in[17];
    const float* b2      = (const float*)d_in[18];
    const int* src = eidx;
    const int* dst = eidx + EE;
    float* out = (float*)d_out;

    cudaFuncSetAttribute(iter_kernel, cudaFuncAttributeMaxDynamicSharedMemorySize, SMEM_IT);

    gate_kernel<<<NPOS, 64>>>(pos_enc, Wg, bg);
    init_h<<<NN, HD>>>(xidx, sel, emb);
    zero_misc<<<(NT * NN + 255) / 256, 256>>>();
    cnt_kernel<<<(EE + 255) / 256, 256>>>(dst, etype);
    scanA<<<98, 1024>>>();
    scanB<<<1, 32>>>();
    scanC<<<(NN + 255) / 256, 256>>>();
    fill_kernel<<<(EE + 255) / 256, 256>>>(src, dst, etype, epos);
    bprep<<<11, 256>>>(Wt, Wih, Whh, W1);

    for (int it = 0; it < 6; it++)
        iter_kernel<<<NT64, 256, SMEM_IT>>>(it & 1, it == 5, bih, bhh, bt,
                                            b1, W2, b2, out);
}